// round 4
// baseline (speedup 1.0000x reference)
#include <cuda_runtime.h>
#include <math.h>

#define NODES 100000
#define EMAX  3200000
#define DIMM  256

// ---------------- scratch (device globals; no allocation allowed) ----------------
__device__ float g_agg[(size_t)NODES * DIMM];
__device__ float g_z  [(size_t)NODES * DIMM];
__device__ float g_h  [(size_t)NODES * DIMM];
__device__ float g_bnsum[DIMM];
__device__ float g_bnsq [DIMM];
// CSR scratch
__device__ int g_deg[NODES];
__device__ int g_off[NODES];
__device__ int g_pos[NODES];
__device__ int g_esrc[EMAX];
__device__ int g_bsum[256];

#define SCAN_CHUNK 512
#define SCAN_NB    196   // ceil(100000/512)

// ---------------- zero ----------------
__global__ void zero_kernel(float4* __restrict__ p, size_t n4) {
    size_t i = (size_t)blockIdx.x * blockDim.x + threadIdx.x;
    size_t stride = (size_t)gridDim.x * blockDim.x;
    float4 z = make_float4(0.f, 0.f, 0.f, 0.f);
    for (; i < n4; i += stride) p[i] = z;
}

// ---------------- CSR build ----------------
__global__ void hist_kernel(const int* __restrict__ dst, int E) {
    int i = blockIdx.x * blockDim.x + threadIdx.x;
    int stride = gridDim.x * blockDim.x;
    for (; i < E; i += stride) atomicAdd(&g_deg[dst[i]], 1);
}

__global__ void scan_blocksum_kernel() {
    int b = blockIdx.x, t = threadIdx.x;
    int i0 = b * SCAN_CHUNK + 2 * t;
    int v = 0;
    if (i0 < NODES)     v += g_deg[i0];
    if (i0 + 1 < NODES) v += g_deg[i0 + 1];
    __shared__ int sm[256];
    sm[t] = v; __syncthreads();
    for (int s = 128; s; s >>= 1) { if (t < s) sm[t] += sm[t + s]; __syncthreads(); }
    if (t == 0) g_bsum[b] = sm[0];
}

__global__ void scan_bases_kernel() {
    int t = threadIdx.x;
    __shared__ int sm[256];
    int orig = (t < SCAN_NB) ? g_bsum[t] : 0;
    sm[t] = orig; __syncthreads();
    for (int off = 1; off < 256; off <<= 1) {
        int v = (t >= off) ? sm[t - off] : 0;
        __syncthreads();
        sm[t] += v;
        __syncthreads();
    }
    if (t < SCAN_NB) g_bsum[t] = sm[t] - orig;   // exclusive
}

__global__ void scan_final_kernel() {
    int b = blockIdx.x, t = threadIdx.x;
    int i0 = b * SCAN_CHUNK + 2 * t;
    int d0 = (i0 < NODES) ? g_deg[i0] : 0;
    int d1 = (i0 + 1 < NODES) ? g_deg[i0 + 1] : 0;
    int pair = d0 + d1;
    __shared__ int sm[256];
    sm[t] = pair; __syncthreads();
    int orig = pair;
    for (int off = 1; off < 256; off <<= 1) {
        int v = (t >= off) ? sm[t - off] : 0;
        __syncthreads();
        sm[t] += v;
        __syncthreads();
    }
    int excl = sm[t] - orig + g_bsum[b];
    if (i0 < NODES)     { g_off[i0] = excl;          g_pos[i0] = excl; }
    if (i0 + 1 < NODES) { g_off[i0 + 1] = excl + d0; g_pos[i0 + 1] = excl + d0; }
}

__global__ void bucket_kernel(const int* __restrict__ src, const int* __restrict__ dst, int E) {
    int i = blockIdx.x * blockDim.x + threadIdx.x;
    int stride = gridDim.x * blockDim.x;
    for (; i < E; i += stride) {
        int d = dst[i];
        int p = atomicAdd(&g_pos[d], 1);
        g_esrc[p] = src[i];
    }
}

// ---------------- atomic-free gather aggregate, 128-column panel ----------------
// agg[n, colOff:colOff+128] = sum_{e in CSR(n)} h[src(e), colOff:colOff+128]
// One warp per node; lane reads one float4 from the panel (warp = 512B per row).
template<int DT>   // total row stride in floats (128 or 256)
__global__ __launch_bounds__(256)
void agg_panel_kernel(const float* __restrict__ h, float* __restrict__ agg, int colOff) {
    int w    = (blockIdx.x * blockDim.x + threadIdx.x) >> 5;
    int lane = threadIdx.x & 31;
    if (w >= NODES) return;
    int node = w;

    const float4* hp = (const float4*)(h + colOff) + lane;
    int beg = g_off[node];
    int cnt = g_deg[node];

    float4 a0 = make_float4(0.f, 0.f, 0.f, 0.f);
    float4 a1 = a0, a2 = a0, a3 = a0;

    for (int i0 = 0; i0 < cnt; i0 += 32) {
        int rem = cnt - i0;
        int n = rem < 32 ? rem : 32;
        int myidx = 0;
        if (i0 + lane < cnt) myidx = __ldg(&g_esrc[beg + i0 + lane]);
        int j = 0;
        for (; j + 4 <= n; j += 4) {
            int s0 = __shfl_sync(0xffffffffu, myidx, j);
            int s1 = __shfl_sync(0xffffffffu, myidx, j + 1);
            int s2 = __shfl_sync(0xffffffffu, myidx, j + 2);
            int s3 = __shfl_sync(0xffffffffu, myidx, j + 3);
            float4 v0 = __ldg(hp + (size_t)s0 * (DT / 4));
            float4 v1 = __ldg(hp + (size_t)s1 * (DT / 4));
            float4 v2 = __ldg(hp + (size_t)s2 * (DT / 4));
            float4 v3 = __ldg(hp + (size_t)s3 * (DT / 4));
            a0.x += v0.x; a0.y += v0.y; a0.z += v0.z; a0.w += v0.w;
            a1.x += v1.x; a1.y += v1.y; a1.z += v1.z; a1.w += v1.w;
            a2.x += v2.x; a2.y += v2.y; a2.z += v2.z; a2.w += v2.w;
            a3.x += v3.x; a3.y += v3.y; a3.z += v3.z; a3.w += v3.w;
        }
        for (; j < n; j++) {
            int s = __shfl_sync(0xffffffffu, myidx, j);
            float4 v = __ldg(hp + (size_t)s * (DT / 4));
            a0.x += v.x; a0.y += v.y; a0.z += v.z; a0.w += v.w;
        }
    }
    a0.x += a1.x + a2.x + a3.x;
    a0.y += a1.y + a2.y + a3.y;
    a0.z += a1.z + a2.z + a3.z;
    a0.w += a1.w + a2.w + a3.w;

    float4* ap = (float4*)(agg + (size_t)node * DT + colOff) + lane;
    *ap = a0;
}

// ---------------- 3xTF32 tensor-core GEMM (software pipelined) ----------------
// C[M,N] = op(A [+A2]) @ B + bias (+ReLU). A row-major [M,K], B row-major [K,N].
// Block tile 128x64, BK=16, 256 threads (8 warps as 4x2), warp tile 32x32.
__device__ __forceinline__ unsigned f2tf32(float x) {
    unsigned r; asm("cvt.rna.tf32.f32 %0, %1;" : "=r"(r) : "f"(x)); return r;
}
__device__ __forceinline__ void mma_tf32(float* c, const unsigned* a, const unsigned* b) {
    asm volatile(
        "mma.sync.aligned.m16n8k8.row.col.f32.tf32.tf32.f32 "
        "{%0,%1,%2,%3}, {%4,%5,%6,%7}, {%8,%9}, {%0,%1,%2,%3};"
        : "+f"(c[0]), "+f"(c[1]), "+f"(c[2]), "+f"(c[3])
        : "r"(a[0]), "r"(a[1]), "r"(a[2]), "r"(a[3]), "r"(b[0]), "r"(b[1]));
}

#define SA 20   // As row stride (floats)
#define SB 72   // Bs row stride (floats)

template<bool ADD2, bool RELU>
__global__ __launch_bounds__(256, 2)
void gemm_tc_kernel(const float* __restrict__ A, const float* __restrict__ A2,
                    const float* __restrict__ B, const float* __restrict__ bias,
                    float* __restrict__ C, int M, int K, int N) {
    __shared__ float As_h[128 * SA];
    __shared__ float As_l[128 * SA];
    __shared__ float Bs_h[16 * SB];
    __shared__ float Bs_l[16 * SB];

    const int tid  = threadIdx.x;
    const int lane = tid & 31;
    const int wid  = tid >> 5;
    const int wm   = wid & 3;
    const int wn   = wid >> 2;
    const int row0 = blockIdx.x * 128;
    const int col0 = blockIdx.y * 64;

    const int lr = lane >> 2;
    const int lc = lane & 3;

    float acc[2][4][4];
    #pragma unroll
    for (int mt = 0; mt < 2; mt++)
        #pragma unroll
        for (int nt = 0; nt < 4; nt++)
            #pragma unroll
            for (int i = 0; i < 4; i++) acc[mt][nt][i] = 0.f;

    const int ar = tid >> 1;
    const int ac = (tid & 1) * 8;
    const int br = tid >> 4;
    const int bc = (tid & 15) * 4;

    const int gr = row0 + ar;
    float va[8], vb[4];

    // ---- prologue load (k0 = 0) ----
    {
        if (gr < M) {
            const float* ap = A + (size_t)gr * K + ac;
            float4 v0 = *(const float4*)(ap);
            float4 v1 = *(const float4*)(ap + 4);
            if (ADD2) {
                const float* a2p = A2 + (size_t)gr * K + ac;
                float4 u0 = *(const float4*)(a2p);
                float4 u1 = *(const float4*)(a2p + 4);
                v0.x += u0.x; v0.y += u0.y; v0.z += u0.z; v0.w += u0.w;
                v1.x += u1.x; v1.y += u1.y; v1.z += u1.z; v1.w += u1.w;
            }
            va[0]=v0.x; va[1]=v0.y; va[2]=v0.z; va[3]=v0.w;
            va[4]=v1.x; va[5]=v1.y; va[6]=v1.z; va[7]=v1.w;
        } else {
            #pragma unroll
            for (int i = 0; i < 8; i++) va[i] = 0.f;
        }
        const float* bp = B + (size_t)br * N + col0 + bc;
        float4 v = *(const float4*)bp;
        vb[0]=v.x; vb[1]=v.y; vb[2]=v.z; vb[3]=v.w;
    }

    for (int k0 = 0; k0 < K; k0 += 16) {
        // ---- split & store current tile ----
        {
            float* dh = &As_h[ar * SA + ac];
            float* dl = &As_l[ar * SA + ac];
            #pragma unroll
            for (int i = 0; i < 8; i++) {
                float hf = __uint_as_float(f2tf32(va[i]));
                dh[i] = hf;
                dl[i] = __uint_as_float(f2tf32(va[i] - hf));
            }
            float* eh = &Bs_h[br * SB + bc];
            float* el = &Bs_l[br * SB + bc];
            #pragma unroll
            for (int i = 0; i < 4; i++) {
                float hf = __uint_as_float(f2tf32(vb[i]));
                eh[i] = hf;
                el[i] = __uint_as_float(f2tf32(vb[i] - hf));
            }
        }
        __syncthreads();

        // ---- prefetch next tile (overlaps with MMA below) ----
        int kn = k0 + 16;
        if (kn < K) {
            if (gr < M) {
                const float* ap = A + (size_t)gr * K + kn + ac;
                float4 v0 = *(const float4*)(ap);
                float4 v1 = *(const float4*)(ap + 4);
                if (ADD2) {
                    const float* a2p = A2 + (size_t)gr * K + kn + ac;
                    float4 u0 = *(const float4*)(a2p);
                    float4 u1 = *(const float4*)(a2p + 4);
                    v0.x += u0.x; v0.y += u0.y; v0.z += u0.z; v0.w += u0.w;
                    v1.x += u1.x; v1.y += u1.y; v1.z += u1.z; v1.w += u1.w;
                }
                va[0]=v0.x; va[1]=v0.y; va[2]=v0.z; va[3]=v0.w;
                va[4]=v1.x; va[5]=v1.y; va[6]=v1.z; va[7]=v1.w;
            }
            const float* bp = B + (size_t)(kn + br) * N + col0 + bc;
            float4 v = *(const float4*)bp;
            vb[0]=v.x; vb[1]=v.y; vb[2]=v.z; vb[3]=v.w;
        }

        // ---- compute on current smem tile ----
        #pragma unroll
        for (int ks = 0; ks < 16; ks += 8) {
            unsigned ah[2][4], al[2][4], bh[4][2], bl[4][2];
            #pragma unroll
            for (int mt = 0; mt < 2; mt++) {
                int rbase = (wm * 32 + mt * 16 + lr) * SA + ks + lc;
                ah[mt][0] = __float_as_uint(As_h[rbase]);
                ah[mt][1] = __float_as_uint(As_h[rbase + 8 * SA]);
                ah[mt][2] = __float_as_uint(As_h[rbase + 4]);
                ah[mt][3] = __float_as_uint(As_h[rbase + 8 * SA + 4]);
                al[mt][0] = __float_as_uint(As_l[rbase]);
                al[mt][1] = __float_as_uint(As_l[rbase + 8 * SA]);
                al[mt][2] = __float_as_uint(As_l[rbase + 4]);
                al[mt][3] = __float_as_uint(As_l[rbase + 8 * SA + 4]);
            }
            #pragma unroll
            for (int nt = 0; nt < 4; nt++) {
                int bbase = (ks + lc) * SB + wn * 32 + nt * 8 + lr;
                bh[nt][0] = __float_as_uint(Bs_h[bbase]);
                bh[nt][1] = __float_as_uint(Bs_h[bbase + 4 * SB]);
                bl[nt][0] = __float_as_uint(Bs_l[bbase]);
                bl[nt][1] = __float_as_uint(Bs_l[bbase + 4 * SB]);
            }
            #pragma unroll
            for (int mt = 0; mt < 2; mt++)
                #pragma unroll
                for (int nt = 0; nt < 4; nt++) {
                    mma_tf32(acc[mt][nt], ah[mt], bh[nt]);
                    mma_tf32(acc[mt][nt], ah[mt], bl[nt]);
                    mma_tf32(acc[mt][nt], al[mt], bh[nt]);
                }
        }
        __syncthreads();
    }

    // ---- epilogue: bias (+relu), write ----
    #pragma unroll
    for (int mt = 0; mt < 2; mt++) {
        int gr0 = row0 + wm * 32 + mt * 16 + lr;
        #pragma unroll
        for (int nt = 0; nt < 4; nt++) {
            int cg = col0 + wn * 32 + nt * 8 + lc * 2;
            float b0 = __ldg(&bias[cg]);
            float b1 = __ldg(&bias[cg + 1]);
            float v0 = acc[mt][nt][0] + b0;
            float v1 = acc[mt][nt][1] + b1;
            float v2 = acc[mt][nt][2] + b0;
            float v3 = acc[mt][nt][3] + b1;
            if (RELU) {
                v0 = fmaxf(v0, 0.f); v1 = fmaxf(v1, 0.f);
                v2 = fmaxf(v2, 0.f); v3 = fmaxf(v3, 0.f);
            }
            if (gr0 < M)     *(float2*)(C + (size_t)gr0 * N + cg)       = make_float2(v0, v1);
            if (gr0 + 8 < M) *(float2*)(C + (size_t)(gr0 + 8) * N + cg) = make_float2(v2, v3);
        }
    }
}

// ---------------- batchnorm stats (per-column sum / sumsq) ----------------
__global__ void bn_stats_kernel(const float* __restrict__ h, int M) {
    int col = threadIdx.x;
    int nb  = gridDim.x;
    int rpb = (M + nb - 1) / nb;
    int r0  = blockIdx.x * rpb;
    int r1  = min(r0 + rpb, M);
    float s = 0.f, q = 0.f;
    for (int r = r0; r < r1; r++) {
        float v = h[(size_t)r * DIMM + col];
        s += v;
        q = fmaf(v, v, q);
    }
    atomicAdd(&g_bnsum[col], s);
    atomicAdd(&g_bnsq[col],  q);
}

// ---------------- batchnorm apply (in place) ----------------
__global__ void bn_apply_kernel(float* __restrict__ h, const float* __restrict__ gamma,
                                const float* __restrict__ beta, int M) {
    __shared__ float sc[DIMM], sh[DIMM];
    int t = threadIdx.x;
    if (t < DIMM) {
        float m   = g_bnsum[t] / (float)M;
        float v   = g_bnsq[t] / (float)M - m * m;
        float inv = rsqrtf(v + 1e-5f);
        float s   = gamma[t] * inv;
        sc[t] = s;
        sh[t] = beta[t] - m * s;
    }
    __syncthreads();
    size_t n4 = (size_t)M * DIMM / 4;
    float4* h4 = (float4*)h;
    for (size_t i = (size_t)blockIdx.x * blockDim.x + t; i < n4;
         i += (size_t)gridDim.x * blockDim.x) {
        int cb = (int)((i * 4) & (DIMM - 1));
        float4 v = h4[i];
        v.x = fmaf(v.x, sc[cb + 0], sh[cb + 0]);
        v.y = fmaf(v.y, sc[cb + 1], sh[cb + 1]);
        v.z = fmaf(v.z, sc[cb + 2], sh[cb + 2]);
        v.w = fmaf(v.w, sc[cb + 3], sh[cb + 3]);
        h4[i] = v;
    }
}

// ---------------- final fc (256->16) + log_softmax, one warp per row ----------------
__global__ void fc_lsm_kernel(const float* __restrict__ h, const float* __restrict__ wfc,
                              const float* __restrict__ bfc, float* __restrict__ out, int M) {
    __shared__ float ws[DIMM * 16];
    for (int i = threadIdx.x; i < DIMM * 16; i += blockDim.x) ws[i] = wfc[i];
    __syncthreads();

    int warp = threadIdx.x >> 5;
    int lane = threadIdx.x & 31;
    int c    = lane & 15;
    int half = lane >> 4;
    int row  = blockIdx.x * 8 + warp;
    if (row >= M) return;

    const float* hr = h + (size_t)row * DIMM;
    float acc = 0.f;
    int kbase = half * 128;
    #pragma unroll 8
    for (int k = 0; k < 128; k++)
        acc = fmaf(hr[kbase + k], ws[(kbase + k) * 16 + c], acc);
    acc += __shfl_xor_sync(0xffffffffu, acc, 16);

    float logit = acc + bfc[c];
    float m = logit;
    #pragma unroll
    for (int off = 8; off; off >>= 1)
        m = fmaxf(m, __shfl_xor_sync(0xffffffffu, m, off));
    float e = expf(logit - m);
    float s = e;
    #pragma unroll
    for (int off = 8; off; off >>= 1)
        s += __shfl_xor_sync(0xffffffffu, s, off);
    float r = logit - m - logf(s);
    if (lane < 16) out[(size_t)row * 16 + c] = r;
}

// ---------------- launch sequence ----------------
static inline void zero_buf(float* p, size_t nfloats) {
    size_t n4 = nfloats / 4;
    int blocks = (int)((n4 + 255) / 256);
    if (blocks > 8192) blocks = 8192;
    if (blocks < 1) blocks = 1;
    zero_kernel<<<blocks, 256>>>((float4*)p, n4);
}

extern "C" void kernel_launch(void* const* d_in, const int* in_sizes, int n_in,
                              void* d_out, int out_size) {
    const float* x   = (const float*)d_in[0];
    const int*   ei  = (const int*)d_in[1];   // int64 in reference -> delivered as int32
    const float* w1a = (const float*)d_in[2];  const float* b1a = (const float*)d_in[3];
    const float* w1b = (const float*)d_in[4];  const float* b1b = (const float*)d_in[5];
    const float* g1  = (const float*)d_in[6];  const float* be1 = (const float*)d_in[7];
    const float* w2a = (const float*)d_in[8];  const float* b2a = (const float*)d_in[9];
    const float* w2b = (const float*)d_in[10]; const float* b2b = (const float*)d_in[11];
    const float* g2  = (const float*)d_in[12]; const float* be2 = (const float*)d_in[13];
    const float* w3a = (const float*)d_in[14]; const float* b3a = (const float*)d_in[15];
    const float* w3b = (const float*)d_in[16]; const float* b3b = (const float*)d_in[17];
    const float* wfc = (const float*)d_in[18]; const float* bfc = (const float*)d_in[19];
    float* out = (float*)d_out;

    const int M = NODES;
    const int E = in_sizes[1] / 2;
    const int* src = ei;
    const int* dst = ei + E;

    float *agg, *z, *h, *bns, *bnq, *degf;
    cudaGetSymbolAddress((void**)&agg, g_agg);
    cudaGetSymbolAddress((void**)&z,   g_z);
    cudaGetSymbolAddress((void**)&h,   g_h);
    cudaGetSymbolAddress((void**)&bns, g_bnsum);
    cudaGetSymbolAddress((void**)&bnq, g_bnsq);
    cudaGetSymbolAddress((void**)&degf, g_deg);

    dim3 ggrid((M + 127) / 128, 4);   // N=256 -> 4 col tiles of 64
    const int EB = (E + 255) / 256;
    const int AGG_BLOCKS = (NODES + 7) / 8;  // 8 warps/block, 1 node/warp
    const int BN_BLOCKS = 512;

    // ---- build CSR (once; reused by all 3 layers) ----
    zero_buf(degf, NODES);
    hist_kernel<<<EB, 256>>>(dst, E);
    scan_blocksum_kernel<<<SCAN_NB, 256>>>();
    scan_bases_kernel<<<1, 256>>>();
    scan_final_kernel<<<SCAN_NB, 256>>>();
    bucket_kernel<<<EB, 256>>>(src, dst, E);

    // ---- conv1 (K=128 aggregation on x; single panel) ----
    agg_panel_kernel<128><<<AGG_BLOCKS, 256>>>(x, agg, 0);
    gemm_tc_kernel<true,  true ><<<ggrid, 256>>>(x, agg, w1a, b1a, z, M, 128, 256);
    gemm_tc_kernel<false, true ><<<ggrid, 256>>>(z, nullptr, w1b, b1b, h, M, 256, 256);
    zero_buf(bns, DIMM); zero_buf(bnq, DIMM);
    bn_stats_kernel<<<BN_BLOCKS, 256>>>(h, M);
    bn_apply_kernel<<<4096, 256>>>(h, g1, be1, M);

    // ---- conv2 (two 128-col panels for L2 residency) ----
    agg_panel_kernel<256><<<AGG_BLOCKS, 256>>>(h, agg, 0);
    agg_panel_kernel<256><<<AGG_BLOCKS, 256>>>(h, agg, 128);
    gemm_tc_kernel<true,  true ><<<ggrid, 256>>>(h, agg, w2a, b2a, z, M, 256, 256);
    gemm_tc_kernel<false, true ><<<ggrid, 256>>>(z, nullptr, w2b, b2b, h, M, 256, 256);
    zero_buf(bns, DIMM); zero_buf(bnq, DIMM);
    bn_stats_kernel<<<BN_BLOCKS, 256>>>(h, M);
    bn_apply_kernel<<<4096, 256>>>(h, g2, be2, M);

    // ---- conv3 ----
    agg_panel_kernel<256><<<AGG_BLOCKS, 256>>>(h, agg, 0);
    agg_panel_kernel<256><<<AGG_BLOCKS, 256>>>(h, agg, 128);
    gemm_tc_kernel<true,  true ><<<ggrid, 256>>>(h, agg, w3a, b3a, z, M, 256, 256);
    gemm_tc_kernel<false, true ><<<ggrid, 256>>>(z, nullptr, w3b, b3b, h, M, 256, 256);

    // ---- fc + log_softmax ----
    fc_lsm_kernel<<<(M + 7) / 8, 256>>>(h, wfc, bfc, out, M);
}

// round 6
// speedup vs baseline: 1.5948x; 1.5948x over previous
#include <cuda_runtime.h>
#include <cuda_fp16.h>
#include <math.h>

#define NODES 100000
#define EMAX  3200000
#define DIMM  256

// ---------------- scratch (device globals; no allocation allowed) ----------------
__device__ float g_agg[(size_t)NODES * DIMM];
__device__ float g_z  [(size_t)NODES * DIMM];
__device__ float g_h  [(size_t)NODES * DIMM];
__device__ __half g_hhalf[(size_t)NODES * DIMM];   // fp16 gather table
__device__ float g_bnsum[DIMM];
__device__ float g_bnsq [DIMM];
// CSR scratch
__device__ int g_deg[NODES];
__device__ int g_off[NODES];
__device__ int g_pos[NODES];
__device__ int g_esrc[EMAX];
__device__ int g_bsum[256];

#define SCAN_CHUNK 512
#define SCAN_NB    196   // ceil(100000/512)

// ---------------- zero ----------------
__global__ void zero_kernel(float4* __restrict__ p, size_t n4) {
    size_t i = (size_t)blockIdx.x * blockDim.x + threadIdx.x;
    size_t stride = (size_t)gridDim.x * blockDim.x;
    float4 z = make_float4(0.f, 0.f, 0.f, 0.f);
    for (; i < n4; i += stride) p[i] = z;
}

// ---------------- CSR build ----------------
__global__ void hist_kernel(const int* __restrict__ dst, int E) {
    int i = blockIdx.x * blockDim.x + threadIdx.x;
    int stride = gridDim.x * blockDim.x;
    for (; i < E; i += stride) atomicAdd(&g_deg[dst[i]], 1);
}

__global__ void scan_blocksum_kernel() {
    int b = blockIdx.x, t = threadIdx.x;
    int i0 = b * SCAN_CHUNK + 2 * t;
    int v = 0;
    if (i0 < NODES)     v += g_deg[i0];
    if (i0 + 1 < NODES) v += g_deg[i0 + 1];
    __shared__ int sm[256];
    sm[t] = v; __syncthreads();
    for (int s = 128; s; s >>= 1) { if (t < s) sm[t] += sm[t + s]; __syncthreads(); }
    if (t == 0) g_bsum[b] = sm[0];
}

__global__ void scan_bases_kernel() {
    int t = threadIdx.x;
    __shared__ int sm[256];
    int orig = (t < SCAN_NB) ? g_bsum[t] : 0;
    sm[t] = orig; __syncthreads();
    for (int off = 1; off < 256; off <<= 1) {
        int v = (t >= off) ? sm[t - off] : 0;
        __syncthreads();
        sm[t] += v;
        __syncthreads();
    }
    if (t < SCAN_NB) g_bsum[t] = sm[t] - orig;   // exclusive
}

__global__ void scan_final_kernel() {
    int b = blockIdx.x, t = threadIdx.x;
    int i0 = b * SCAN_CHUNK + 2 * t;
    int d0 = (i0 < NODES) ? g_deg[i0] : 0;
    int d1 = (i0 + 1 < NODES) ? g_deg[i0 + 1] : 0;
    int pair = d0 + d1;
    __shared__ int sm[256];
    sm[t] = pair; __syncthreads();
    int orig = pair;
    for (int off = 1; off < 256; off <<= 1) {
        int v = (t >= off) ? sm[t - off] : 0;
        __syncthreads();
        sm[t] += v;
        __syncthreads();
    }
    int excl = sm[t] - orig + g_bsum[b];
    if (i0 < NODES)     { g_off[i0] = excl;          g_pos[i0] = excl; }
    if (i0 + 1 < NODES) { g_off[i0 + 1] = excl + d0; g_pos[i0 + 1] = excl + d0; }
}

__global__ void bucket_kernel(const int* __restrict__ src, const int* __restrict__ dst, int E) {
    int i = blockIdx.x * blockDim.x + threadIdx.x;
    int stride = gridDim.x * blockDim.x;
    for (; i < E; i += stride) {
        int d = dst[i];
        int p = atomicAdd(&g_pos[d], 1);
        g_esrc[p] = src[i];
    }
}

// ---------------- fp32 -> fp16 convert ----------------
__global__ void convert_half_kernel(const float* __restrict__ in, __half* __restrict__ outh, size_t n) {
    size_t i = ((size_t)blockIdx.x * blockDim.x + threadIdx.x) * 4;
    size_t stride = (size_t)gridDim.x * blockDim.x * 4;
    for (; i < n; i += stride) {
        float4 v = *(const float4*)(in + i);
        __half2 h0 = __floats2half2_rn(v.x, v.y);
        __half2 h1 = __floats2half2_rn(v.z, v.w);
        *(uint2*)(outh + i) = make_uint2(*(unsigned*)&h0, *(unsigned*)&h1);
    }
}

// ---------------- atomic-free gather aggregate over fp16 table ----------------
// agg[n] = sum_{e in CSR(n)} hh[src(e)]  (fp16 in, fp32 accumulate/out)
// One warp per node (grid-stride). D=256: lane reads uint4 (8 halves);
// D=128: lane reads uint2 (4 halves). Whole row per warp, fully coalesced.
template<int D>
__global__ __launch_bounds__(256)
void agg_half_kernel(const __half* __restrict__ hh, float* __restrict__ agg) {
    int w    = (blockIdx.x * blockDim.x + threadIdx.x) >> 5;
    int lane = threadIdx.x & 31;
    int nw   = (gridDim.x * blockDim.x) >> 5;
    for (int node = w; node < NODES; node += nw) {
        int beg = g_off[node];
        int cnt = g_deg[node];
        if (D == 256) {
            const uint4* hp = (const uint4*)hh + lane;   // row stride = 32 uint4
            float a[8] = {0.f,0.f,0.f,0.f,0.f,0.f,0.f,0.f};
            float b[8] = {0.f,0.f,0.f,0.f,0.f,0.f,0.f,0.f};
            int i = 0;
            for (; i + 2 <= cnt; i += 2) {
                int s0 = __ldg(&g_esrc[beg + i]);
                int s1 = __ldg(&g_esrc[beg + i + 1]);
                uint4 v0 = __ldg(hp + (size_t)s0 * 32);
                uint4 v1 = __ldg(hp + (size_t)s1 * 32);
                float2 f;
                f = __half22float2(*(__half2*)&v0.x); a[0]+=f.x; a[1]+=f.y;
                f = __half22float2(*(__half2*)&v0.y); a[2]+=f.x; a[3]+=f.y;
                f = __half22float2(*(__half2*)&v0.z); a[4]+=f.x; a[5]+=f.y;
                f = __half22float2(*(__half2*)&v0.w); a[6]+=f.x; a[7]+=f.y;
                f = __half22float2(*(__half2*)&v1.x); b[0]+=f.x; b[1]+=f.y;
                f = __half22float2(*(__half2*)&v1.y); b[2]+=f.x; b[3]+=f.y;
                f = __half22float2(*(__half2*)&v1.z); b[4]+=f.x; b[5]+=f.y;
                f = __half22float2(*(__half2*)&v1.w); b[6]+=f.x; b[7]+=f.y;
            }
            if (i < cnt) {
                int s = __ldg(&g_esrc[beg + i]);
                uint4 v = __ldg(hp + (size_t)s * 32);
                float2 f;
                f = __half22float2(*(__half2*)&v.x); a[0]+=f.x; a[1]+=f.y;
                f = __half22float2(*(__half2*)&v.y); a[2]+=f.x; a[3]+=f.y;
                f = __half22float2(*(__half2*)&v.z); a[4]+=f.x; a[5]+=f.y;
                f = __half22float2(*(__half2*)&v.w); a[6]+=f.x; a[7]+=f.y;
            }
            float4* ap = (float4*)(agg + (size_t)node * 256 + lane * 8);
            ap[0] = make_float4(a[0]+b[0], a[1]+b[1], a[2]+b[2], a[3]+b[3]);
            ap[1] = make_float4(a[4]+b[4], a[5]+b[5], a[6]+b[6], a[7]+b[7]);
        } else {
            const uint2* hp = (const uint2*)hh + lane;   // row stride = 32 uint2
            float a[4] = {0.f,0.f,0.f,0.f};
            float b[4] = {0.f,0.f,0.f,0.f};
            int i = 0;
            for (; i + 2 <= cnt; i += 2) {
                int s0 = __ldg(&g_esrc[beg + i]);
                int s1 = __ldg(&g_esrc[beg + i + 1]);
                uint2 v0 = __ldg(hp + (size_t)s0 * 32);
                uint2 v1 = __ldg(hp + (size_t)s1 * 32);
                float2 f;
                f = __half22float2(*(__half2*)&v0.x); a[0]+=f.x; a[1]+=f.y;
                f = __half22float2(*(__half2*)&v0.y); a[2]+=f.x; a[3]+=f.y;
                f = __half22float2(*(__half2*)&v1.x); b[0]+=f.x; b[1]+=f.y;
                f = __half22float2(*(__half2*)&v1.y); b[2]+=f.x; b[3]+=f.y;
            }
            if (i < cnt) {
                int s = __ldg(&g_esrc[beg + i]);
                uint2 v = __ldg(hp + (size_t)s * 32);
                float2 f;
                f = __half22float2(*(__half2*)&v.x); a[0]+=f.x; a[1]+=f.y;
                f = __half22float2(*(__half2*)&v.y); a[2]+=f.x; a[3]+=f.y;
            }
            *(float4*)(agg + (size_t)node * 128 + lane * 4) =
                make_float4(a[0]+b[0], a[1]+b[1], a[2]+b[2], a[3]+b[3]);
        }
    }
}

// ---------------- 3xTF32 tensor-core GEMM (R3 version) ----------------
__device__ __forceinline__ unsigned f2tf32(float x) {
    unsigned r; asm("cvt.rna.tf32.f32 %0, %1;" : "=r"(r) : "f"(x)); return r;
}
__device__ __forceinline__ void mma_tf32(float* c, const unsigned* a, const unsigned* b) {
    asm volatile(
        "mma.sync.aligned.m16n8k8.row.col.f32.tf32.tf32.f32 "
        "{%0,%1,%2,%3}, {%4,%5,%6,%7}, {%8,%9}, {%0,%1,%2,%3};"
        : "+f"(c[0]), "+f"(c[1]), "+f"(c[2]), "+f"(c[3])
        : "r"(a[0]), "r"(a[1]), "r"(a[2]), "r"(a[3]), "r"(b[0]), "r"(b[1]));
}

#define SA 20
#define SB 72

template<bool ADD2, bool RELU>
__global__ __launch_bounds__(256, 2)
void gemm_tc_kernel(const float* __restrict__ A, const float* __restrict__ A2,
                    const float* __restrict__ B, const float* __restrict__ bias,
                    float* __restrict__ C, int M, int K, int N) {
    __shared__ float As_h[128 * SA];
    __shared__ float As_l[128 * SA];
    __shared__ float Bs_h[16 * SB];
    __shared__ float Bs_l[16 * SB];

    const int tid  = threadIdx.x;
    const int lane = tid & 31;
    const int wid  = tid >> 5;
    const int wm   = wid & 3;
    const int wn   = wid >> 2;
    const int row0 = blockIdx.x * 128;
    const int col0 = blockIdx.y * 64;

    const int lr = lane >> 2;
    const int lc = lane & 3;

    float acc[2][4][4];
    #pragma unroll
    for (int mt = 0; mt < 2; mt++)
        #pragma unroll
        for (int nt = 0; nt < 4; nt++)
            #pragma unroll
            for (int i = 0; i < 4; i++) acc[mt][nt][i] = 0.f;

    const int ar = tid >> 1;
    const int ac = (tid & 1) * 8;
    const int br = tid >> 4;
    const int bc = (tid & 15) * 4;

    for (int k0 = 0; k0 < K; k0 += 16) {
        {
            int gr = row0 + ar;
            float va[8];
            if (gr < M) {
                const float* ap = A + (size_t)gr * K + k0 + ac;
                float4 v0 = *(const float4*)(ap);
                float4 v1 = *(const float4*)(ap + 4);
                if (ADD2) {
                    const float* a2p = A2 + (size_t)gr * K + k0 + ac;
                    float4 u0 = *(const float4*)(a2p);
                    float4 u1 = *(const float4*)(a2p + 4);
                    v0.x += u0.x; v0.y += u0.y; v0.z += u0.z; v0.w += u0.w;
                    v1.x += u1.x; v1.y += u1.y; v1.z += u1.z; v1.w += u1.w;
                }
                va[0]=v0.x; va[1]=v0.y; va[2]=v0.z; va[3]=v0.w;
                va[4]=v1.x; va[5]=v1.y; va[6]=v1.z; va[7]=v1.w;
            } else {
                #pragma unroll
                for (int i = 0; i < 8; i++) va[i] = 0.f;
            }
            float* dh = &As_h[ar * SA + ac];
            float* dl = &As_l[ar * SA + ac];
            #pragma unroll
            for (int i = 0; i < 8; i++) {
                float hf = __uint_as_float(f2tf32(va[i]));
                dh[i] = hf;
                dl[i] = __uint_as_float(f2tf32(va[i] - hf));
            }
        }
        {
            const float* bp = B + (size_t)(k0 + br) * N + col0 + bc;
            float4 v = *(const float4*)bp;
            float vb[4] = {v.x, v.y, v.z, v.w};
            float* dh = &Bs_h[br * SB + bc];
            float* dl = &Bs_l[br * SB + bc];
            #pragma unroll
            for (int i = 0; i < 4; i++) {
                float hf = __uint_as_float(f2tf32(vb[i]));
                dh[i] = hf;
                dl[i] = __uint_as_float(f2tf32(vb[i] - hf));
            }
        }
        __syncthreads();

        #pragma unroll
        for (int ks = 0; ks < 16; ks += 8) {
            unsigned ah[2][4], al[2][4], bh[4][2], bl[4][2];
            #pragma unroll
            for (int mt = 0; mt < 2; mt++) {
                int rbase = (wm * 32 + mt * 16 + lr) * SA + ks + lc;
                ah[mt][0] = __float_as_uint(As_h[rbase]);
                ah[mt][1] = __float_as_uint(As_h[rbase + 8 * SA]);
                ah[mt][2] = __float_as_uint(As_h[rbase + 4]);
                ah[mt][3] = __float_as_uint(As_h[rbase + 8 * SA + 4]);
                al[mt][0] = __float_as_uint(As_l[rbase]);
                al[mt][1] = __float_as_uint(As_l[rbase + 8 * SA]);
                al[mt][2] = __float_as_uint(As_l[rbase + 4]);
                al[mt][3] = __float_as_uint(As_l[rbase + 8 * SA + 4]);
            }
            #pragma unroll
            for (int nt = 0; nt < 4; nt++) {
                int bbase = (ks + lc) * SB + wn * 32 + nt * 8 + lr;
                bh[nt][0] = __float_as_uint(Bs_h[bbase]);
                bh[nt][1] = __float_as_uint(Bs_h[bbase + 4 * SB]);
                bl[nt][0] = __float_as_uint(Bs_l[bbase]);
                bl[nt][1] = __float_as_uint(Bs_l[bbase + 4 * SB]);
            }
            #pragma unroll
            for (int mt = 0; mt < 2; mt++)
                #pragma unroll
                for (int nt = 0; nt < 4; nt++) {
                    mma_tf32(acc[mt][nt], ah[mt], bh[nt]);
                    mma_tf32(acc[mt][nt], ah[mt], bl[nt]);
                    mma_tf32(acc[mt][nt], al[mt], bh[nt]);
                }
        }
        __syncthreads();
    }

    #pragma unroll
    for (int mt = 0; mt < 2; mt++) {
        int gr0 = row0 + wm * 32 + mt * 16 + lr;
        #pragma unroll
        for (int nt = 0; nt < 4; nt++) {
            int cg = col0 + wn * 32 + nt * 8 + lc * 2;
            float b0 = __ldg(&bias[cg]);
            float b1 = __ldg(&bias[cg + 1]);
            float v0 = acc[mt][nt][0] + b0;
            float v1 = acc[mt][nt][1] + b1;
            float v2 = acc[mt][nt][2] + b0;
            float v3 = acc[mt][nt][3] + b1;
            if (RELU) {
                v0 = fmaxf(v0, 0.f); v1 = fmaxf(v1, 0.f);
                v2 = fmaxf(v2, 0.f); v3 = fmaxf(v3, 0.f);
            }
            if (gr0 < M)     *(float2*)(C + (size_t)gr0 * N + cg)       = make_float2(v0, v1);
            if (gr0 + 8 < M) *(float2*)(C + (size_t)(gr0 + 8) * N + cg) = make_float2(v2, v3);
        }
    }
}

// ---------------- batchnorm stats ----------------
__global__ void bn_stats_kernel(const float* __restrict__ h, int M) {
    int col = threadIdx.x;
    int nb  = gridDim.x;
    int rpb = (M + nb - 1) / nb;
    int r0  = blockIdx.x * rpb;
    int r1  = min(r0 + rpb, M);
    float s = 0.f, q = 0.f;
    for (int r = r0; r < r1; r++) {
        float v = h[(size_t)r * DIMM + col];
        s += v;
        q = fmaf(v, v, q);
    }
    atomicAdd(&g_bnsum[col], s);
    atomicAdd(&g_bnsq[col],  q);
}

// ---------------- batchnorm apply (in place) + fp16 copy ----------------
__global__ void bn_apply_kernel(float* __restrict__ h, __half* __restrict__ hh,
                                const float* __restrict__ gamma,
                                const float* __restrict__ beta, int M) {
    __shared__ float sc[DIMM], sh[DIMM];
    int t = threadIdx.x;
    if (t < DIMM) {
        float m   = g_bnsum[t] / (float)M;
        float v   = g_bnsq[t] / (float)M - m * m;
        float inv = rsqrtf(v + 1e-5f);
        float s   = gamma[t] * inv;
        sc[t] = s;
        sh[t] = beta[t] - m * s;
    }
    __syncthreads();
    size_t n4 = (size_t)M * DIMM / 4;
    float4* h4 = (float4*)h;
    uint2*  hh4 = (uint2*)hh;
    for (size_t i = (size_t)blockIdx.x * blockDim.x + t; i < n4;
         i += (size_t)gridDim.x * blockDim.x) {
        int cb = (int)((i * 4) & (DIMM - 1));
        float4 v = h4[i];
        v.x = fmaf(v.x, sc[cb + 0], sh[cb + 0]);
        v.y = fmaf(v.y, sc[cb + 1], sh[cb + 1]);
        v.z = fmaf(v.z, sc[cb + 2], sh[cb + 2]);
        v.w = fmaf(v.w, sc[cb + 3], sh[cb + 3]);
        h4[i] = v;
        __half2 p0 = __floats2half2_rn(v.x, v.y);
        __half2 p1 = __floats2half2_rn(v.z, v.w);
        hh4[i] = make_uint2(*(unsigned*)&p0, *(unsigned*)&p1);
    }
}

// ---------------- final fc (256->16) + log_softmax ----------------
__global__ void fc_lsm_kernel(const float* __restrict__ h, const float* __restrict__ wfc,
                              const float* __restrict__ bfc, float* __restrict__ out, int M) {
    __shared__ float ws[DIMM * 16];
    for (int i = threadIdx.x; i < DIMM * 16; i += blockDim.x) ws[i] = wfc[i];
    __syncthreads();

    int warp = threadIdx.x >> 5;
    int lane = threadIdx.x & 31;
    int c    = lane & 15;
    int half = lane >> 4;
    int row  = blockIdx.x * 8 + warp;
    if (row >= M) return;

    const float* hr = h + (size_t)row * DIMM;
    float acc = 0.f;
    int kbase = half * 128;
    #pragma unroll 8
    for (int k = 0; k < 128; k++)
        acc = fmaf(hr[kbase + k], ws[(kbase + k) * 16 + c], acc);
    acc += __shfl_xor_sync(0xffffffffu, acc, 16);

    float logit = acc + bfc[c];
    float m = logit;
    #pragma unroll
    for (int off = 8; off; off >>= 1)
        m = fmaxf(m, __shfl_xor_sync(0xffffffffu, m, off));
    float e = expf(logit - m);
    float s = e;
    #pragma unroll
    for (int off = 8; off; off >>= 1)
        s += __shfl_xor_sync(0xffffffffu, s, off);
    float r = logit - m - logf(s);
    if (lane < 16) out[(size_t)row * 16 + c] = r;
}

// ---------------- launch sequence ----------------
static inline void zero_buf(float* p, size_t nfloats) {
    size_t n4 = nfloats / 4;
    int blocks = (int)((n4 + 255) / 256);
    if (blocks > 8192) blocks = 8192;
    if (blocks < 1) blocks = 1;
    zero_kernel<<<blocks, 256>>>((float4*)p, n4);
}

extern "C" void kernel_launch(void* const* d_in, const int* in_sizes, int n_in,
                              void* d_out, int out_size) {
    const float* x   = (const float*)d_in[0];
    const int*   ei  = (const int*)d_in[1];   // int64 in reference -> delivered as int32
    const float* w1a = (const float*)d_in[2];  const float* b1a = (const float*)d_in[3];
    const float* w1b = (const float*)d_in[4];  const float* b1b = (const float*)d_in[5];
    const float* g1  = (const float*)d_in[6];  const float* be1 = (const float*)d_in[7];
    const float* w2a = (const float*)d_in[8];  const float* b2a = (const float*)d_in[9];
    const float* w2b = (const float*)d_in[10]; const float* b2b = (const float*)d_in[11];
    const float* g2  = (const float*)d_in[12]; const float* be2 = (const float*)d_in[13];
    const float* w3a = (const float*)d_in[14]; const float* b3a = (const float*)d_in[15];
    const float* w3b = (const float*)d_in[16]; const float* b3b = (const float*)d_in[17];
    const float* wfc = (const float*)d_in[18]; const float* bfc = (const float*)d_in[19];
    float* out = (float*)d_out;

    const int M = NODES;
    const int E = in_sizes[1] / 2;
    const int* src = ei;
    const int* dst = ei + E;

    float *agg, *z, *h, *bns, *bnq, *degf;
    __half* hh;
    cudaGetSymbolAddress((void**)&agg, g_agg);
    cudaGetSymbolAddress((void**)&z,   g_z);
    cudaGetSymbolAddress((void**)&h,   g_h);
    cudaGetSymbolAddress((void**)&hh,  g_hhalf);
    cudaGetSymbolAddress((void**)&bns, g_bnsum);
    cudaGetSymbolAddress((void**)&bnq, g_bnsq);
    cudaGetSymbolAddress((void**)&degf, g_deg);

    dim3 ggrid((M + 127) / 128, 4);
    const int EB = (E + 255) / 256;
    const int AGG_BLOCKS = 6250;      // 50000 warps, grid-stride
    const int BN_BLOCKS = 512;

    // ---- build CSR (once) ----
    zero_buf(degf, NODES);
    hist_kernel<<<EB, 256>>>(dst, E);
    scan_blocksum_kernel<<<SCAN_NB, 256>>>();
    scan_bases_kernel<<<1, 256>>>();
    scan_final_kernel<<<SCAN_NB, 256>>>();
    bucket_kernel<<<EB, 256>>>(src, dst, E);

    // ---- conv1: convert x to fp16, gather in fp16 ----
    convert_half_kernel<<<4096, 256>>>(x, hh, (size_t)M * 128);
    agg_half_kernel<128><<<AGG_BLOCKS, 256>>>(hh, agg);
    gemm_tc_kernel<true,  true ><<<ggrid, 256>>>(x, agg, w1a, b1a, z, M, 128, 256);
    gemm_tc_kernel<false, true ><<<ggrid, 256>>>(z, nullptr, w1b, b1b, h, M, 256, 256);
    zero_buf(bns, DIMM); zero_buf(bnq, DIMM);
    bn_stats_kernel<<<BN_BLOCKS, 256>>>(h, M);
    bn_apply_kernel<<<4096, 256>>>(h, hh, g1, be1, M);   // writes fp16 copy too

    // ---- conv2 ----
    agg_half_kernel<256><<<AGG_BLOCKS, 256>>>(hh, agg);
    gemm_tc_kernel<true,  true ><<<ggrid, 256>>>(h, agg, w2a, b2a, z, M, 256, 256);
    gemm_tc_kernel<false, true ><<<ggrid, 256>>>(z, nullptr, w2b, b2b, h, M, 256, 256);
    zero_buf(bns, DIMM); zero_buf(bnq, DIMM);
    bn_stats_kernel<<<BN_BLOCKS, 256>>>(h, M);
    bn_apply_kernel<<<4096, 256>>>(h, hh, g2, be2, M);

    // ---- conv3 ----
    agg_half_kernel<256><<<AGG_BLOCKS, 256>>>(hh, agg);
    gemm_tc_kernel<true,  true ><<<ggrid, 256>>>(h, agg, w3a, b3a, z, M, 256, 256);
    gemm_tc_kernel<false, true ><<<ggrid, 256>>>(z, nullptr, w3b, b3b, h, M, 256, 256);

    // ---- fc + log_softmax ----
    fc_lsm_kernel<<<(M + 7) / 8, 256>>>(h, wfc, bfc, out, M);
}